// round 16
// baseline (speedup 1.0000x reference)
#include <cuda_runtime.h>
#include <math.h>

#define BB 4
#define NN 2048
#define HH 4
#define DD 128
#define QB 128   // queries per CTA in tensor attention
#define QBO 64   // rows per CTA in outproj
#define PCKH 24  // fp16 packed-row stride (words)
#define AJW 68   // adjb row stride (words, 16B-aligned)

// ---- device scratch ----
__device__ float g_h[(size_t)BB * HH * NN * DD];          // [b,h,n,o]
__device__ __align__(16) unsigned g_htp[(size_t)BB * HH * 64 * DD * 16]; // fp16 h tiles
__device__ __align__(16) unsigned g_wtp[(size_t)BB * HH * 64 * NN * 16]; // fp16 w tiles
__device__ __align__(16) unsigned g_attp[(size_t)BB * NN * 256]; // fp16 concat(att) words
__device__ float g_es[BB * HH * NN];
__device__ float g_es2[BB * HH * NN];
__device__ float g_ed[BB * HH * NN];
__device__ float g_ed2[BB * HH * NN];
__device__ __align__(16) unsigned g_wph[DD][256];         // out_proj_w fp16 [col][word]
__device__ __align__(16) unsigned g_adjb[(size_t)BB * NN * 64]; // adjacency bitmask

// ---- packed fp32x2 helpers ----
#define FMA2(d, a, b, c) \
    asm("fma.rn.f32x2 %0, %1, %2, %3;" : "=l"(d) : "l"(a), "l"(b), "l"(c))
#define PACK2(d, x) \
    asm("mov.b64 %0, {%1, %1};" : "=l"(d) : "r"(__float_as_uint(x)))
__device__ __forceinline__ float lo2(unsigned long long v) {
    return __uint_as_float((unsigned)(v & 0xffffffffull));
}
__device__ __forceinline__ float hi2(unsigned long long v) {
    return __uint_as_float((unsigned)(v >> 32));
}

__device__ __forceinline__ unsigned f2h2(float lo, float hi) {
    unsigned r;
    asm("cvt.rn.f16x2.f32 %0, %1, %2;" : "=r"(r) : "f"(hi), "f"(lo));
    return r;
}

__device__ __forceinline__ void mma_f16(float* c, unsigned a0, unsigned a1,
                                        unsigned a2, unsigned a3,
                                        unsigned b0, unsigned b1) {
    asm volatile(
        "mma.sync.aligned.m16n8k16.row.col.f32.f16.f16.f32 "
        "{%0,%1,%2,%3}, {%4,%5,%6,%7}, {%8,%9}, {%0,%1,%2,%3};"
        : "+f"(c[0]), "+f"(c[1]), "+f"(c[2]), "+f"(c[3])
        : "r"(a0), "r"(a1), "r"(a2), "r"(a3), "r"(b0), "r"(b1));
}

__device__ __forceinline__ void cp_async16(unsigned smem_addr, const void* gptr) {
    asm volatile("cp.async.cg.shared.global [%0], [%1], 16;"
                 :: "r"(smem_addr), "l"(gptr) : "memory");
}
#define CP_COMMIT() asm volatile("cp.async.commit_group;" ::: "memory")
#define CP_WAIT0() asm volatile("cp.async.wait_group 0;" ::: "memory")

// ============================================================
// Kernel -1: pack adjacency -> bitmask. warp per row.
// ============================================================
__global__ void k_packadj(const int* __restrict__ adj) {
    int wid = threadIdx.x >> 5, lane = threadIdx.x & 31;
    size_t row = (size_t)blockIdx.x * 8 + wid;
    const int4* arow = (const int4*)(adj + row * NN);
    unsigned* dst = g_adjb + row * 64;
#pragma unroll 4
    for (int it = 0; it < 16; it++) {
        int4 v = arow[it * 32 + lane];
        unsigned nib = (v.x != 0 ? 1u : 0u) | (v.y != 0 ? 2u : 0u) |
                       (v.z != 0 ? 4u : 0u) | (v.w != 0 ? 8u : 0u);
        unsigned nv = nib << (4 * (lane & 7));
        nv |= __shfl_xor_sync(0xffffffffu, nv, 1);
        nv |= __shfl_xor_sync(0xffffffffu, nv, 2);
        nv |= __shfl_xor_sync(0xffffffffu, nv, 4);
        if ((lane & 7) == 0) dst[it * 4 + (lane >> 3)] = nv;
    }
}

// ============================================================
// Kernel 0: pack out_proj_w -> fp16 words [col][w], w = k-pair
// ============================================================
__global__ void k_prepw(const float* __restrict__ Wp) {
    int idx = blockIdx.x * 256 + threadIdx.x;  // 32768 total
    int col = idx & 127, w = idx >> 7;
    g_wph[col][w] = f2h2(Wp[(2 * w) * DD + col], Wp[(2 * w + 1) * DD + col]);
}

// ============================================================
// Kernel 1: h = x @ W per head; writes g_h and fp16 tiles g_htp
// ============================================================
__global__ void k_project(const float* __restrict__ x, const float* __restrict__ W) {
    __shared__ __align__(16) float xs_t[DD][20];
    __shared__ float ht_s[DD][17];
    int b = blockIdx.y, n0 = blockIdx.x * 16, tid = threadIdx.x;
#pragma unroll
    for (int i = 0; i < 8; i++) {
        int j = tid + i * 256;
        int r = j >> 7, k = j & 127;
        xs_t[k][r] = x[((size_t)b * NN + n0 + r) * DD + k];
    }
    __syncthreads();
    int col = tid & 127, rs = tid >> 7;
    for (int h = 0; h < HH; h++) {
        const float* Wh = W + h * DD * DD + col;
        unsigned long long acc[4] = {0ull, 0ull, 0ull, 0ull};
#pragma unroll 8
        for (int k = 0; k < DD; k++) {
            unsigned long long wp;
            PACK2(wp, Wh[k * DD]);
            ulonglong2 x01 = *(const ulonglong2*)&xs_t[k][rs * 8];
            ulonglong2 x23 = *(const ulonglong2*)&xs_t[k][rs * 8 + 4];
            FMA2(acc[0], wp, x01.x, acc[0]);
            FMA2(acc[1], wp, x01.y, acc[1]);
            FMA2(acc[2], wp, x23.x, acc[2]);
            FMA2(acc[3], wp, x23.y, acc[3]);
        }
        size_t base = ((size_t)(b * HH + h) * NN + n0 + rs * 8) * DD + col;
#pragma unroll
        for (int p = 0; p < 4; p++) {
            float vlo = lo2(acc[p]), vhi = hi2(acc[p]);
            g_h[base + (size_t)(2 * p) * DD] = vlo;
            g_h[base + (size_t)(2 * p + 1) * DD] = vhi;
            ht_s[col][rs * 8 + 2 * p] = vlo;
            ht_s[col][rs * 8 + 2 * p + 1] = vhi;
        }
        __syncthreads();
        // write fp16 tile words (LINEAR: word w = m-pair (2w, 2w+1))
        {
            int o = tid >> 1, j0 = (tid & 1) * 8;
            int chunk = n0 >> 5;
            int w0 = ((n0 & 31) + j0) >> 1;
            unsigned* dst =
                g_htp + (((size_t)(b * HH + h) * 64 + chunk) * DD + o) * 16 + w0;
#pragma unroll
            for (int t = 0; t < 4; t++)
                dst[t] = f2h2(ht_s[o][j0 + 2 * t], ht_s[o][j0 + 2 * t + 1]);
        }
        __syncthreads();
    }
}

// ============================================================
// Kernel 2: scores -> 4 exps per (b,h,n)
// ============================================================
__global__ void k_scores(const float* __restrict__ a) {
    int warp = (blockIdx.x * blockDim.x + threadIdx.x) >> 5;
    int lane = threadIdx.x & 31;
    int hidx = (warp / NN) % HH;
    float4 hv = ((const float4*)(g_h + (size_t)warp * DD))[lane];
    float4 av = ((const float4*)(a + hidx * 2 * DD))[lane];
    float4 bv = ((const float4*)(a + hidx * 2 * DD + DD))[lane];
    float s = hv.x * av.x + hv.y * av.y + hv.z * av.z + hv.w * av.w;
    float d = hv.x * bv.x + hv.y * bv.y + hv.z * bv.z + hv.w * bv.w;
#pragma unroll
    for (int off = 16; off; off >>= 1) {
        s += __shfl_down_sync(0xffffffffu, s, off);
        d += __shfl_down_sync(0xffffffffu, d, off);
    }
    if (!lane) {
        g_es[warp] = expf(s);
        g_es2[warp] = expf(0.2f * s);
        g_ed[warp] = expf(d);
        g_ed2[warp] = expf(0.2f * d);
    }
}

// ============================================================
// Kernel 3a: producer — Z pass + w values. Writes fp32 alpha
// and fp16-packed w tiles (g_wtp) for the GEMM kernel.
// CTA = (b,h) x 128 queries. Pure streaming.
// ============================================================
__global__ void __launch_bounds__(256, 3)
k_walpha(float* __restrict__ alpha, int write_alpha) {
    __shared__ __align__(16) float ed_s[NN], ed2_s[NN];   // 16 KB
    __shared__ __align__(16) unsigned adjb[QB][AJW];      // 34.8 KB
    __shared__ float esr[QB], es2r[QB], izr[QB];

    int b = blockIdx.z, hh = blockIdx.y, q0 = blockIdx.x * QB;
    int bh = b * HH + hh;
    int tid = threadIdx.x, wid = tid >> 5, lane = tid & 31;

    const float* edp = g_ed + bh * NN;
    const float* ed2p = g_ed2 + bh * NN;
    for (int m = tid; m < NN; m += 256) {
        ed_s[m] = edp[m];
        ed2_s[m] = ed2p[m];
    }
    if (tid < QB) {
        int idx = bh * NN + q0 + tid;
        esr[tid] = g_es[idx];
        es2r[tid] = g_es2[idx];
    }
    {
        int r = tid >> 1, j0 = (tid & 1) * 32;
        const uint4* src =
            (const uint4*)(g_adjb + ((size_t)(b * NN + q0 + r)) * 64 + j0);
#pragma unroll
        for (int u = 0; u < 8; u++) *(uint4*)&adjb[r][j0 + u * 4] = src[u];
    }
    __syncthreads();

    // Z per row (16 rows per warp)
#pragma unroll
    for (int rr = 0; rr < 16; rr++) {
        int r = wid * 16 + rr;
        float es = esr[r], es2 = es2r[r];
        float z = 0.f;
        for (int j = 0; j < NN / 32; j++) {
            unsigned w = adjb[r][j];
            if ((w >> lane) & 1u) {
                int m = j * 32 + lane;
                z += fmaxf(es * ed_s[m], es2 * ed2_s[m]);
            }
        }
#pragma unroll
        for (int off = 16; off; off >>= 1) z += __shfl_down_sync(0xffffffffu, z, off);
        if (!lane) izr[r] = z;
    }
    __syncthreads();
    if (tid < QB) izr[tid] = 1.0f / izr[tid];
    __syncthreads();

    // w production: thread (q = tid>>1, g2 = tid&1), m = 32c + 16g2 .. +15
    int q = tid >> 1, g2 = tid & 1;
    float* alrow = alpha + ((size_t)bh * NN + q0 + q) * NN;
    float p1 = esr[q] * izr[q], p2 = es2r[q] * izr[q];
    unsigned* wbase =
        g_wtp + ((size_t)bh * 64 * NN + (q0 + q)) * 16 + 8 * g2;

    for (int c = 0; c < NN / 32; c++) {
        int m0 = c * 32 + 16 * g2;
        unsigned pb = adjb[q][c] >> (16 * g2);
        unsigned wpk[8];
        {
            float4 e0 = *(const float4*)&ed_s[m0];
            float4 e1 = *(const float4*)&ed_s[m0 + 4];
            float4 f0 = *(const float4*)&ed2_s[m0];
            float4 f1 = *(const float4*)&ed2_s[m0 + 4];
            float w0 = (pb & 1u) ? fmaxf(p1 * e0.x, p2 * f0.x) : 0.f;
            float w1 = (pb & 2u) ? fmaxf(p1 * e0.y, p2 * f0.y) : 0.f;
            float w2 = (pb & 4u) ? fmaxf(p1 * e0.z, p2 * f0.z) : 0.f;
            float w3 = (pb & 8u) ? fmaxf(p1 * e0.w, p2 * f0.w) : 0.f;
            float w4 = (pb & 16u) ? fmaxf(p1 * e1.x, p2 * f1.x) : 0.f;
            float w5 = (pb & 32u) ? fmaxf(p1 * e1.y, p2 * f1.y) : 0.f;
            float w6 = (pb & 64u) ? fmaxf(p1 * e1.z, p2 * f1.z) : 0.f;
            float w7 = (pb & 128u) ? fmaxf(p1 * e1.w, p2 * f1.w) : 0.f;
            if (write_alpha) {
                *(float4*)(alrow + m0) = make_float4(w0, w1, w2, w3);
                *(float4*)(alrow + m0 + 4) = make_float4(w4, w5, w6, w7);
            }
            wpk[0] = f2h2(w0, w1); wpk[1] = f2h2(w2, w3);
            wpk[2] = f2h2(w4, w5); wpk[3] = f2h2(w6, w7);
        }
        {
            float4 e0 = *(const float4*)&ed_s[m0 + 8];
            float4 e1 = *(const float4*)&ed_s[m0 + 12];
            float4 f0 = *(const float4*)&ed2_s[m0 + 8];
            float4 f1 = *(const float4*)&ed2_s[m0 + 12];
            unsigned pc = pb >> 8;
            float w0 = (pc & 1u) ? fmaxf(p1 * e0.x, p2 * f0.x) : 0.f;
            float w1 = (pc & 2u) ? fmaxf(p1 * e0.y, p2 * f0.y) : 0.f;
            float w2 = (pc & 4u) ? fmaxf(p1 * e0.z, p2 * f0.z) : 0.f;
            float w3 = (pc & 8u) ? fmaxf(p1 * e0.w, p2 * f0.w) : 0.f;
            float w4 = (pc & 16u) ? fmaxf(p1 * e1.x, p2 * f1.x) : 0.f;
            float w5 = (pc & 32u) ? fmaxf(p1 * e1.y, p2 * f1.y) : 0.f;
            float w6 = (pc & 64u) ? fmaxf(p1 * e1.z, p2 * f1.z) : 0.f;
            float w7 = (pc & 128u) ? fmaxf(p1 * e1.w, p2 * f1.w) : 0.f;
            if (write_alpha) {
                *(float4*)(alrow + m0 + 8) = make_float4(w0, w1, w2, w3);
                *(float4*)(alrow + m0 + 12) = make_float4(w4, w5, w6, w7);
            }
            wpk[4] = f2h2(w0, w1); wpk[5] = f2h2(w2, w3);
            wpk[6] = f2h2(w4, w5); wpk[7] = f2h2(w6, w7);
        }
        unsigned* wd = wbase + (size_t)c * NN * 16;
        *(uint4*)wd = make_uint4(wpk[0], wpk[1], wpk[2], wpk[3]);
        *(uint4*)(wd + 4) = make_uint4(wpk[4], wpk[5], wpk[6], wpk[7]);
    }
}

// ============================================================
// Kernel 3b: pure fp16 GEMM attention. CTA = (b,h) x 128 q,
// warp tile 32q x 64o. Both tiles via cp.async, double-buffered.
// ============================================================
__global__ void __launch_bounds__(256, 2)
k_attn_mma() {
    __shared__ __align__(16) unsigned h_pack[2][DD * PCKH];    // 24.6 KB
    __shared__ __align__(16) unsigned w_pack[2][QB * PCKH];    // 24.6 KB

    int b = blockIdx.z, hh = blockIdx.y, q0 = blockIdx.x * QB;
    int bh = b * HH + hh;
    int tid = threadIdx.x, wid = tid >> 5, lane = tid & 31;

    float acc[2][8][4];
#pragma unroll
    for (int i = 0; i < 2; i++)
#pragma unroll
        for (int j = 0; j < 8; j++)
#pragma unroll
            for (int k = 0; k < 4; k++) acc[i][j][k] = 0.f;

    // staging: thread owns row r = tid>>1, 16B pair at 8*half
    int r = tid >> 1, half = tid & 1;
    const uint4* hsrc = (const uint4*)(g_htp + ((size_t)bh * 64 * DD + r) * 16);
    const uint4* wsrc =
        (const uint4*)(g_wtp + ((size_t)bh * 64 * NN + q0 + r) * 16);
    unsigned hdst =
        (unsigned)__cvta_generic_to_shared(&h_pack[0][r * PCKH + 8 * half]);
    unsigned wdst =
        (unsigned)__cvta_generic_to_shared(&w_pack[0][r * PCKH + 8 * half]);
    const unsigned HBUF = DD * PCKH * 4;
    const unsigned WBUF = QB * PCKH * 4;

    // warp tile: 32q x 64o
    int wq0 = (wid >> 1) * 32, oh = (wid & 1) * 64;
    int frow = lane >> 2, tig = lane & 3, fcol = tig * 2;

    // prologue: chunk 0
    {
        const uint4* hs = hsrc + 2 * half;
        cp_async16(hdst, hs);
        cp_async16(hdst + 16, hs + 1);
        const uint4* ws = wsrc + 2 * half;
        cp_async16(wdst, ws);
        cp_async16(wdst + 16, ws + 1);
        CP_COMMIT();
    }

    for (int c = 0; c < NN / 32; c++) {
        int buf = c & 1;
        CP_WAIT0();       // chunk c landed
        __syncthreads();  // visible to all; MMA(c-1) on buf^1 done

        // issue chunk c+1 into buf^1
        if (c < NN / 32 - 1) {
            const uint4* hs = hsrc + (size_t)(c + 1) * DD * 4 + 2 * half;
            unsigned hd = hdst + (buf ^ 1) * HBUF;
            cp_async16(hd, hs);
            cp_async16(hd + 16, hs + 1);
            const uint4* ws = wsrc + (size_t)(c + 1) * NN * 4 + 2 * half;
            unsigned wd = wdst + (buf ^ 1) * WBUF;
            cp_async16(wd, ws);
            cp_async16(wd + 16, ws + 1);
            CP_COMMIT();
        }

        // MMA: 32q x 64o x 32m per warp (fp16, k16)
#pragma unroll
        for (int ks = 0; ks < 2; ks++) {
            int wcol = ks * 8 + 2 * tig;
            uint2 a0 = *(const uint2*)&w_pack[buf][(wq0 + frow) * PCKH + wcol];
            uint2 a1 = *(const uint2*)&w_pack[buf][(wq0 + 8 + frow) * PCKH + wcol];
            uint2 a2 = *(const uint2*)&w_pack[buf][(wq0 + 16 + frow) * PCKH + wcol];
            uint2 a3 = *(const uint2*)&w_pack[buf][(wq0 + 24 + frow) * PCKH + wcol];
#pragma unroll
            for (int nt = 0; nt < 8; nt++) {
                uint2 bb =
                    *(const uint2*)&h_pack[buf][(oh + nt * 8 + frow) * PCKH + wcol];
                mma_f16(acc[0][nt], a0.x, a1.x, a0.y, a1.y, bb.x, bb.y);
                mma_f16(acc[1][nt], a2.x, a3.x, a2.y, a3.y, bb.x, bb.y);
            }
        }
    }

    // epilogue: write fp16-packed concat words for outproj
#pragma unroll
    for (int qb = 0; qb < 2; qb++)
#pragma unroll
        for (int nt = 0; nt < 8; nt++) {
            int n = q0 + wq0 + qb * 16 + frow;
            int wrd = hh * 64 + ((oh + nt * 8) >> 1) + tig;
            unsigned* p = g_attp + ((size_t)b * NN + n) * 256 + wrd;
            p[0] = f2h2(acc[qb][nt][0], acc[qb][nt][1]);
            p[8 * 256] = f2h2(acc[qb][nt][2], acc[qb][nt][3]);
        }
}

// ============================================================
// Kernel 4: out = concat(att) @ Wp + bias, fp16 warp-MMA.
// ============================================================
__global__ void __launch_bounds__(256, 3)
k_outproj_f16(const float* __restrict__ bias, float* __restrict__ out) {
    __shared__ __align__(16) unsigned a_pack[2][QBO * PCKH];  // 12.3 KB
    __shared__ __align__(16) unsigned b_pack[2][DD * PCKH];   // 24.6 KB
    __shared__ float bias_s[DD];

    int tid = threadIdx.x, wid = tid >> 5, lane = tid & 31;
    int row0 = blockIdx.x * QBO;
    if (tid < DD) bias_s[tid] = bias[tid];
    __syncthreads();

    float acc[2][4][4];
#pragma unroll
    for (int i = 0; i < 2; i++)
#pragma unroll
        for (int j = 0; j < 4; j++)
#pragma unroll
            for (int k = 0; k < 4; k++) acc[i][j][k] = 0.f;

    int a_row = (tid >> 6) * 16 + ((tid >> 1) & 15);
    int a_quad = (tid & 1) + 2 * ((tid >> 5) & 1);
    const uint4* asrc =
        (const uint4*)(g_attp + (size_t)(row0 + a_row) * 256) + a_quad;

    int b_col = tid >> 1, b_half = tid & 1;
    const uint4* bsrc = (const uint4*)&g_wph[b_col][0];

    int wq0 = (wid >> 2) * 32, oh = (wid & 3) * 32;
    int frow = lane >> 2, tig = lane & 3, fcol = tig * 2;

    uint4 areg = asrc[0];
    uint4 breg0 = bsrc[b_half];
    uint4 breg1 = bsrc[2 + b_half];

    for (int c = 0; c < 16; c++) {
        int buf = c & 1;
        *(uint4*)&a_pack[buf][a_row * PCKH + a_quad * 4] = areg;
        *(uint4*)&b_pack[buf][b_col * PCKH + 4 * b_half] = breg0;
        *(uint4*)&b_pack[buf][b_col * PCKH + 8 + 4 * b_half] = breg1;

        if (c < 15) {
            areg = asrc[(c + 1) * 4];
            breg0 = bsrc[(c + 1) * 4 + b_half];
            breg1 = bsrc[(c + 1) * 4 + 2 + b_half];
        }
        __syncthreads();

#pragma unroll
        for (int ks = 0; ks < 2; ks++) {
            int wcol = ks * 8 + 2 * tig;
            uint2 aA0 = *(const uint2*)&a_pack[buf][(wq0 + frow) * PCKH + wcol];
            uint2 aA1 = *(const uint2*)&a_pack[buf][(wq0 + 8 + frow) * PCKH + wcol];
            uint2 aB0 = *(const uint2*)&a_pack[buf][(wq0 + 16 + frow) * PCKH + wcol];
            uint2 aB1 = *(const uint2*)&a_pack[buf][(wq0 + 24 + frow) * PCKH + wcol];
#pragma unroll
            for (int nt = 0; nt < 4; nt++) {
                uint2 bb =
                    *(const uint2*)&b_pack[buf][(oh + nt * 8 + frow) * PCKH + wcol];
                mma_f16(acc[0][nt], aA0.x, aA1.x, aA0.y, aA1.y, bb.x, bb.y);
                mma_f16(acc[1][nt], aB0.x, aB1.x, aB0.y, aB1.y, bb.x, bb.y);
            }
        }
        __syncthreads();
    }

#pragma unroll
    for (int qb = 0; qb < 2; qb++)
#pragma unroll
        for (int nt = 0; nt < 4; nt++) {
            int rr = row0 + wq0 + qb * 16 + frow;
            int oo = oh + nt * 8 + fcol;
            float b0 = bias_s[oo], b1 = bias_s[oo + 1];
            float* p0 = out + (size_t)rr * DD + oo;
            *(float2*)p0 = make_float2(acc[qb][nt][0] + b0, acc[qb][nt][1] + b1);
            *(float2*)(p0 + (size_t)8 * DD) =
                make_float2(acc[qb][nt][2] + b0, acc[qb][nt][3] + b1);
        }
}

// ============================================================
extern "C" void kernel_launch(void* const* d_in, const int* in_sizes, int n_in,
                              void* d_out, int out_size) {
    const float* x    = (const float*)d_in[0];
    const int*   adj  = (const int*)d_in[1];
    const float* W    = (const float*)d_in[2];
    const float* a    = (const float*)d_in[3];
    const float* Wp   = (const float*)d_in[4];
    const float* bias = (const float*)d_in[5];

    const size_t OUT_E = (size_t)BB * NN * DD;
    const size_t AL_E  = (size_t)BB * HH * NN * NN;

    float* outp = nullptr;
    float* alphap = nullptr;
    int write_alpha = 0, write_out = 0;

    if ((size_t)out_size >= OUT_E + AL_E) {
        outp = (float*)d_out;
        alphap = (float*)d_out + OUT_E;
        write_alpha = 1;
        write_out = 1;
    } else if ((size_t)out_size >= AL_E) {
        alphap = (float*)d_out;
        write_alpha = 1;
    } else {
        outp = (float*)d_out;
        write_out = 1;
    }
    if (!alphap) alphap = g_h;  // dummy, never stored to when !write_alpha

    k_packadj<<<(BB * NN) / 8, 256>>>(adj);
    k_project<<<dim3(NN / 16, BB), 256>>>(x, W);
    k_scores<<<(BB * HH * NN * 32) / 256, 256>>>(a);
    k_walpha<<<dim3(NN / QB, HH, BB), 256>>>(alphap, write_alpha);
    k_attn_mma<<<dim3(NN / QB, HH, BB), 256>>>();
    if (write_out) {
        k_prepw<<<128, 256>>>(Wp);
        k_outproj_f16<<<(BB * NN) / QBO, 256>>>(bias, outp);
    }
}

// round 17
// speedup vs baseline: 1.3819x; 1.3819x over previous
#include <cuda_runtime.h>
#include <math.h>

#define BB 4
#define NN 2048
#define HH 4
#define DD 128
#define QB 128   // queries per CTA in tensor attention
#define QBO 64   // rows per CTA in outproj
#define PCKA 20  // attn packed-row stride (words) — ldmatrix conflict-free
#define PCKH 24  // outproj packed-row stride (words)
#define AJW 68   // adjb row stride (words, 16B-aligned)

// ---- device scratch ----
__device__ float g_h[(size_t)BB * HH * NN * DD];          // [b,h,n,o]
__device__ __align__(16) unsigned g_htp[(size_t)BB * HH * 64 * DD * 16]; // fp16 h tiles (linear words)
__device__ __align__(16) unsigned g_attp[(size_t)BB * NN * 256]; // fp16 concat(att) words
__device__ float g_es[BB * HH * NN];
__device__ float g_es2[BB * HH * NN];
__device__ float g_ed[BB * HH * NN];
__device__ float g_ed2[BB * HH * NN];
__device__ __align__(16) unsigned g_wph[DD][256];         // out_proj_w fp16 [col][word]
__device__ __align__(16) unsigned g_adjb[(size_t)BB * NN * 64]; // adjacency bitmask

// ---- packed fp32x2 helpers ----
#define FMA2(d, a, b, c) \
    asm("fma.rn.f32x2 %0, %1, %2, %3;" : "=l"(d) : "l"(a), "l"(b), "l"(c))
#define PACK2(d, x) \
    asm("mov.b64 %0, {%1, %1};" : "=l"(d) : "r"(__float_as_uint(x)))
__device__ __forceinline__ float lo2(unsigned long long v) {
    return __uint_as_float((unsigned)(v & 0xffffffffull));
}
__device__ __forceinline__ float hi2(unsigned long long v) {
    return __uint_as_float((unsigned)(v >> 32));
}

__device__ __forceinline__ unsigned f2h2(float lo, float hi) {
    unsigned r;
    asm("cvt.rn.f16x2.f32 %0, %1, %2;" : "=r"(r) : "f"(hi), "f"(lo));
    return r;
}

__device__ __forceinline__ void mma_f16(float* c, unsigned a0, unsigned a1,
                                        unsigned a2, unsigned a3,
                                        unsigned b0, unsigned b1) {
    asm volatile(
        "mma.sync.aligned.m16n8k16.row.col.f32.f16.f16.f32 "
        "{%0,%1,%2,%3}, {%4,%5,%6,%7}, {%8,%9}, {%0,%1,%2,%3};"
        : "+f"(c[0]), "+f"(c[1]), "+f"(c[2]), "+f"(c[3])
        : "r"(a0), "r"(a1), "r"(a2), "r"(a3), "r"(b0), "r"(b1));
}

__device__ __forceinline__ void ldsm_x4(unsigned& r0, unsigned& r1, unsigned& r2,
                                        unsigned& r3, unsigned addr) {
    asm volatile("ldmatrix.sync.aligned.m8n8.x4.shared.b16 {%0,%1,%2,%3}, [%4];"
                 : "=r"(r0), "=r"(r1), "=r"(r2), "=r"(r3) : "r"(addr));
}

__device__ __forceinline__ void cp_async16(unsigned smem_addr, const void* gptr) {
    asm volatile("cp.async.cg.shared.global [%0], [%1], 16;"
                 :: "r"(smem_addr), "l"(gptr) : "memory");
}
#define CP_COMMIT() asm volatile("cp.async.commit_group;" ::: "memory")
#define CP_WAIT0() asm volatile("cp.async.wait_group 0;" ::: "memory")

// ============================================================
// Kernel -1: pack adjacency -> bitmask. warp per row.
// ============================================================
__global__ void k_packadj(const int* __restrict__ adj) {
    int wid = threadIdx.x >> 5, lane = threadIdx.x & 31;
    size_t row = (size_t)blockIdx.x * 8 + wid;
    const int4* arow = (const int4*)(adj + row * NN);
    unsigned* dst = g_adjb + row * 64;
#pragma unroll 4
    for (int it = 0; it < 16; it++) {
        int4 v = arow[it * 32 + lane];
        unsigned nib = (v.x != 0 ? 1u : 0u) | (v.y != 0 ? 2u : 0u) |
                       (v.z != 0 ? 4u : 0u) | (v.w != 0 ? 8u : 0u);
        unsigned nv = nib << (4 * (lane & 7));
        nv |= __shfl_xor_sync(0xffffffffu, nv, 1);
        nv |= __shfl_xor_sync(0xffffffffu, nv, 2);
        nv |= __shfl_xor_sync(0xffffffffu, nv, 4);
        if ((lane & 7) == 0) dst[it * 4 + (lane >> 3)] = nv;
    }
}

// ============================================================
// Kernel 0: pack out_proj_w -> fp16 words [col][w], w = k-pair
// ============================================================
__global__ void k_prepw(const float* __restrict__ Wp) {
    int idx = blockIdx.x * 256 + threadIdx.x;  // 32768 total
    int col = idx & 127, w = idx >> 7;
    g_wph[col][w] = f2h2(Wp[(2 * w) * DD + col], Wp[(2 * w + 1) * DD + col]);
}

// ============================================================
// Kernel 1: h = x @ W per head; writes g_h and fp16 tiles g_htp
// ============================================================
__global__ void k_project(const float* __restrict__ x, const float* __restrict__ W) {
    __shared__ __align__(16) float xs_t[DD][20];
    __shared__ float ht_s[DD][17];
    int b = blockIdx.y, n0 = blockIdx.x * 16, tid = threadIdx.x;
#pragma unroll
    for (int i = 0; i < 8; i++) {
        int j = tid + i * 256;
        int r = j >> 7, k = j & 127;
        xs_t[k][r] = x[((size_t)b * NN + n0 + r) * DD + k];
    }
    __syncthreads();
    int col = tid & 127, rs = tid >> 7;
    for (int h = 0; h < HH; h++) {
        const float* Wh = W + h * DD * DD + col;
        unsigned long long acc[4] = {0ull, 0ull, 0ull, 0ull};
#pragma unroll 8
        for (int k = 0; k < DD; k++) {
            unsigned long long wp;
            PACK2(wp, Wh[k * DD]);
            ulonglong2 x01 = *(const ulonglong2*)&xs_t[k][rs * 8];
            ulonglong2 x23 = *(const ulonglong2*)&xs_t[k][rs * 8 + 4];
            FMA2(acc[0], wp, x01.x, acc[0]);
            FMA2(acc[1], wp, x01.y, acc[1]);
            FMA2(acc[2], wp, x23.x, acc[2]);
            FMA2(acc[3], wp, x23.y, acc[3]);
        }
        size_t base = ((size_t)(b * HH + h) * NN + n0 + rs * 8) * DD + col;
#pragma unroll
        for (int p = 0; p < 4; p++) {
            float vlo = lo2(acc[p]), vhi = hi2(acc[p]);
            g_h[base + (size_t)(2 * p) * DD] = vlo;
            g_h[base + (size_t)(2 * p + 1) * DD] = vhi;
            ht_s[col][rs * 8 + 2 * p] = vlo;
            ht_s[col][rs * 8 + 2 * p + 1] = vhi;
        }
        __syncthreads();
        // write fp16 tile words (LINEAR: word w = m-pair (2w, 2w+1))
        {
            int o = tid >> 1, j0 = (tid & 1) * 8;
            int chunk = n0 >> 5;
            int w0 = ((n0 & 31) + j0) >> 1;
            unsigned* dst =
                g_htp + (((size_t)(b * HH + h) * 64 + chunk) * DD + o) * 16 + w0;
#pragma unroll
            for (int t = 0; t < 4; t++)
                dst[t] = f2h2(ht_s[o][j0 + 2 * t], ht_s[o][j0 + 2 * t + 1]);
        }
        __syncthreads();
    }
}

// ============================================================
// Kernel 2: scores -> 4 exps per (b,h,n)
// ============================================================
__global__ void k_scores(const float* __restrict__ a) {
    int warp = (blockIdx.x * blockDim.x + threadIdx.x) >> 5;
    int lane = threadIdx.x & 31;
    int hidx = (warp / NN) % HH;
    float4 hv = ((const float4*)(g_h + (size_t)warp * DD))[lane];
    float4 av = ((const float4*)(a + hidx * 2 * DD))[lane];
    float4 bv = ((const float4*)(a + hidx * 2 * DD + DD))[lane];
    float s = hv.x * av.x + hv.y * av.y + hv.z * av.z + hv.w * av.w;
    float d = hv.x * bv.x + hv.y * bv.y + hv.z * bv.z + hv.w * bv.w;
#pragma unroll
    for (int off = 16; off; off >>= 1) {
        s += __shfl_down_sync(0xffffffffu, s, off);
        d += __shfl_down_sync(0xffffffffu, d, off);
    }
    if (!lane) {
        g_es[warp] = expf(s);
        g_es2[warp] = expf(0.2f * s);
        g_ed[warp] = expf(d);
        g_ed2[warp] = expf(0.2f * d);
    }
}

// ============================================================
// Kernel 3: fused fp16 warp-MMA attention. CTA = (b,h) x 128 q,
// warp tile 32q x 64o. ldmatrix fragment loads, cp.async h
// staging, double-buffered, 1 barrier/chunk, producer after MMA.
// ============================================================
__global__ void __launch_bounds__(256, 2)
k_attn_mma(float* __restrict__ alpha, int write_alpha) {
    __shared__ __align__(16) float ed_s[NN], ed2_s[NN];        // 16 KB
    __shared__ __align__(16) unsigned adjb[QB][AJW];           // 34.8 KB
    __shared__ __align__(16) unsigned h_pack[2][DD * PCKA];    // 20.5 KB
    __shared__ __align__(16) unsigned w_pack[2][QB * PCKA];    // 20.5 KB
    __shared__ float esr[QB], es2r[QB], izr[QB];

    int b = blockIdx.z, hh = blockIdx.y, q0 = blockIdx.x * QB;
    int bh = b * HH + hh;
    int tid = threadIdx.x, wid = tid >> 5, lane = tid & 31;

    const float* edp = g_ed + bh * NN;
    const float* ed2p = g_ed2 + bh * NN;
    for (int m = tid; m < NN; m += 256) {
        ed_s[m] = edp[m];
        ed2_s[m] = ed2p[m];
    }
    if (tid < QB) {
        int idx = bh * NN + q0 + tid;
        esr[tid] = g_es[idx];
        es2r[tid] = g_es2[idx];
    }
    {
        int r = tid >> 1, j0 = (tid & 1) * 32;
        const uint4* src =
            (const uint4*)(g_adjb + ((size_t)(b * NN + q0 + r)) * 64 + j0);
#pragma unroll
        for (int u = 0; u < 8; u++) *(uint4*)&adjb[r][j0 + u * 4] = src[u];
    }
    __syncthreads();

    // ---- Z per row from bits (16 rows per warp) ----
#pragma unroll
    for (int rr = 0; rr < 16; rr++) {
        int r = wid * 16 + rr;
        float es = esr[r], es2 = es2r[r];
        float z = 0.f;
        for (int j = 0; j < NN / 32; j++) {
            unsigned w = adjb[r][j];
            if ((w >> lane) & 1u) {
                int m = j * 32 + lane;
                z += fmaxf(es * ed_s[m], es2 * ed2_s[m]);
            }
        }
#pragma unroll
        for (int off = 16; off; off >>= 1) z += __shfl_down_sync(0xffffffffu, z, off);
        if (!lane) izr[r] = z;
    }
    __syncthreads();
    if (tid < QB) izr[tid] = 1.0f / izr[tid];
    __syncthreads();

    // ---- pipelined main loop ----
    float acc[2][8][4];
#pragma unroll
    for (int i = 0; i < 2; i++)
#pragma unroll
        for (int j = 0; j < 8; j++)
#pragma unroll
            for (int k = 0; k < 4; k++) acc[i][j][k] = 0.f;

    // h staging via cp.async: thread owns row r, 16B pair at 8*half
    int ro = tid >> 1, half = tid & 1;
    const uint4* hsrc = (const uint4*)(g_htp + ((size_t)bh * 64 * DD + ro) * 16);
    unsigned hdst =
        (unsigned)__cvta_generic_to_shared(&h_pack[0][ro * PCKA + 8 * half]);
    const unsigned HBUF = DD * PCKA * 4;
    const unsigned WBUF = QB * PCKA * 4;

    // w producer: thread (q = tid>>1, g2 = tid&1) handles m = 32c + 16g2 .. +15
    int q = tid >> 1, g2 = tid & 1;
    float* alrow = alpha + ((size_t)bh * NN + q0 + q) * NN;
    float p1 = esr[q] * izr[q], p2 = es2r[q] * izr[q];

    // warp tile: 32q x 64o
    int wq0 = (wid >> 1) * 32, oh = (wid & 1) * 64;
    int frow = lane >> 2, tig = lane & 3, fcol = tig * 2;

    // ldmatrix per-lane base addresses
    unsigned a_base = (unsigned)__cvta_generic_to_shared(
        &w_pack[0][(wq0 + ((lane >> 3) & 1) * 8 + (lane & 7)) * PCKA +
                   ((lane >> 4) & 1) * 4]);
    unsigned b_base = (unsigned)__cvta_generic_to_shared(
        &h_pack[0][(oh + (lane >> 4) * 8 + (lane & 7)) * PCKA +
                   ((lane >> 3) & 1) * 4]);

    unsigned wpk[8];

#define PRODUCE_W(cc)                                                          \
    do {                                                                       \
        int m0 = (cc) * 32 + 16 * g2;                                          \
        unsigned pb = adjb[q][cc] >> (16 * g2);                                \
        {                                                                      \
            float4 e0 = *(const float4*)&ed_s[m0];                             \
            float4 e1 = *(const float4*)&ed_s[m0 + 4];                         \
            float4 f0 = *(const float4*)&ed2_s[m0];                            \
            float4 f1 = *(const float4*)&ed2_s[m0 + 4];                        \
            float w0 = (pb & 1u) ? fmaxf(p1 * e0.x, p2 * f0.x) : 0.f;          \
            float w1 = (pb & 2u) ? fmaxf(p1 * e0.y, p2 * f0.y) : 0.f;          \
            float w2 = (pb & 4u) ? fmaxf(p1 * e0.z, p2 * f0.z) : 0.f;          \
            float w3 = (pb & 8u) ? fmaxf(p1 * e0.w, p2 * f0.w) : 0.f;          \
            float w4 = (pb & 16u) ? fmaxf(p1 * e1.x, p2 * f1.x) : 0.f;         \
            float w5 = (pb & 32u) ? fmaxf(p1 * e1.y, p2 * f1.y) : 0.f;         \
            float w6 = (pb & 64u) ? fmaxf(p1 * e1.z, p2 * f1.z) : 0.f;         \
            float w7 = (pb & 128u) ? fmaxf(p1 * e1.w, p2 * f1.w) : 0.f;        \
            if (write_alpha) {                                                 \
                *(float4*)(alrow + m0) = make_float4(w0, w1, w2, w3);          \
                *(float4*)(alrow + m0 + 4) = make_float4(w4, w5, w6, w7);      \
            }                                                                  \
            wpk[0] = f2h2(w0, w1); wpk[1] = f2h2(w2, w3);                      \
            wpk[2] = f2h2(w4, w5); wpk[3] = f2h2(w6, w7);                      \
        }                                                                      \
        {                                                                      \
            float4 e0 = *(const float4*)&ed_s[m0 + 8];                         \
            float4 e1 = *(const float4*)&ed_s[m0 + 12];                        \
            float4 f0 = *(const float4*)&ed2_s[m0 + 8];                        \
            float4 f1 = *(const float4*)&ed2_s[m0 + 12];                       \
            unsigned pc = pb >> 8;                                             \
            float w0 = (pc & 1u) ? fmaxf(p1 * e0.x, p2 * f0.x) : 0.f;          \
            float w1 = (pc & 2u) ? fmaxf(p1 * e0.y, p2 * f0.y) : 0.f;          \
            float w2 = (pc & 4u) ? fmaxf(p1 * e0.z, p2 * f0.z) : 0.f;          \
            float w3 = (pc & 8u) ? fmaxf(p1 * e0.w, p2 * f0.w) : 0.f;          \
            float w4 = (pc & 16u) ? fmaxf(p1 * e1.x, p2 * f1.x) : 0.f;         \
            float w5 = (pc & 32u) ? fmaxf(p1 * e1.y, p2 * f1.y) : 0.f;         \
            float w6 = (pc & 64u) ? fmaxf(p1 * e1.z, p2 * f1.z) : 0.f;         \
            float w7 = (pc & 128u) ? fmaxf(p1 * e1.w, p2 * f1.w) : 0.f;        \
            if (write_alpha) {                                                 \
                *(float4*)(alrow + m0 + 8) = make_float4(w0, w1, w2, w3);      \
                *(float4*)(alrow + m0 + 12) = make_float4(w4, w5, w6, w7);     \
            }                                                                  \
            wpk[4] = f2h2(w0, w1); wpk[5] = f2h2(w2, w3);                      \
            wpk[6] = f2h2(w4, w5); wpk[7] = f2h2(w6, w7);                      \
        }                                                                      \
    } while (0)

    // prologue: chunk 0
    {
        const uint4* s = hsrc + 2 * half;
        cp_async16(hdst, s);
        cp_async16(hdst + 16, s + 1);
        CP_COMMIT();
    }
    PRODUCE_W(0);

    for (int c = 0; c < NN / 32; c++) {
        int buf = c & 1;
        // stage chunk c w-tile from regs
        *(uint4*)&w_pack[buf][q * PCKA + 8 * g2] =
            make_uint4(wpk[0], wpk[1], wpk[2], wpk[3]);
        *(uint4*)&w_pack[buf][q * PCKA + 8 * g2 + 4] =
            make_uint4(wpk[4], wpk[5], wpk[6], wpk[7]);

        CP_WAIT0();       // h chunk c landed
        __syncthreads();  // all staging visible; MMA(c-1) on buf^1 done

        // issue h chunk c+1 into buf^1
        if (c < NN / 32 - 1) {
            const uint4* s = hsrc + (size_t)(c + 1) * DD * 4 + 2 * half;
            unsigned d = hdst + (buf ^ 1) * HBUF;
            cp_async16(d, s);
            cp_async16(d + 16, s + 1);
            CP_COMMIT();
        }

        // MMA: 32q x 64o x 32m per warp via ldmatrix
        {
            unsigned abase = a_base + buf * WBUF;
            unsigned bbase = b_base + buf * HBUF;
#pragma unroll
            for (int ks = 0; ks < 2; ks++) {
                unsigned a0, a1, a2, a3, c0, c1, c2, c3;
                ldsm_x4(a0, a1, a2, a3, abase + ks * 32);
                ldsm_x4(c0, c1, c2, c3, abase + ks * 32 + 16 * PCKA * 4);
#pragma unroll
                for (int g = 0; g < 4; g++) {
                    unsigned b0, b1, b2, b3;
                    ldsm_x4(b0, b1, b2, b3, bbase + ks * 32 + g * 16 * PCKA * 4);
                    mma_f16(acc[0][2 * g], a0, a1, a2, a3, b0, b1);
                    mma_f16(acc[0][2 * g + 1], a0, a1, a2, a3, b2, b3);
                    mma_f16(acc[1][2 * g], c0, c1, c2, c3, b0, b1);
                    mma_f16(acc[1][2 * g + 1], c0, c1, c2, c3, b2, b3);
                }
            }
        }

        // producer math for chunk c+1 (after MMA, before next barrier)
        if (c < NN / 32 - 1) PRODUCE_W(c + 1);
    }
#undef PRODUCE_W

    // epilogue: write fp16-packed concat words for outproj
#pragma unroll
    for (int qb = 0; qb < 2; qb++)
#pragma unroll
        for (int nt = 0; nt < 8; nt++) {
            int n = q0 + wq0 + qb * 16 + frow;
            int wrd = hh * 64 + ((oh + nt * 8) >> 1) + tig;
            unsigned* p = g_attp + ((size_t)b * NN + n) * 256 + wrd;
            p[0] = f2h2(acc[qb][nt][0], acc[qb][nt][1]);
            p[8 * 256] = f2h2(acc[qb][nt][2], acc[qb][nt][3]);
        }
}

// ============================================================
// Kernel 4: out = concat(att) @ Wp + bias, fp16 warp-MMA.
// ============================================================
__global__ void __launch_bounds__(256, 3)
k_outproj_f16(const float* __restrict__ bias, float* __restrict__ out) {
    __shared__ __align__(16) unsigned a_pack[2][QBO * PCKH];  // 12.3 KB
    __shared__ __align__(16) unsigned b_pack[2][DD * PCKH];   // 24.6 KB
    __shared__ float bias_s[DD];

    int tid = threadIdx.x, wid = tid >> 5, lane = tid & 31;
    int row0 = blockIdx.x * QBO;
    if (tid < DD) bias_s[tid] = bias[tid];
    __syncthreads();

    float acc[2][4][4];
#pragma unroll
    for (int i = 0; i < 2; i++)
#pragma unroll
        for (int j = 0; j < 4; j++)
#pragma unroll
            for (int k = 0; k < 4; k++) acc[i][j][k] = 0.f;

    int a_row = (tid >> 6) * 16 + ((tid >> 1) & 15);
    int a_quad = (tid & 1) + 2 * ((tid >> 5) & 1);
    const uint4* asrc =
        (const uint4*)(g_attp + (size_t)(row0 + a_row) * 256) + a_quad;

    int b_col = tid >> 1, b_half = tid & 1;
    const uint4* bsrc = (const uint4*)&g_wph[b_col][0];

    int wq0 = (wid >> 2) * 32, oh = (wid & 3) * 32;
    int frow = lane >> 2, tig = lane & 3, fcol = tig * 2;

    uint4 areg = asrc[0];
    uint4 breg0 = bsrc[b_half];
    uint4 breg1 = bsrc[2 + b_half];

    for (int c = 0; c < 16; c++) {
        int buf = c & 1;
        *(uint4*)&a_pack[buf][a_row * PCKH + a_quad * 4] = areg;
        *(uint4*)&b_pack[buf][b_col * PCKH + 4 * b_half] = breg0;
        *(uint4*)&b_pack[buf][b_col * PCKH + 8 + 4 * b_half] = breg1;

        if (c < 15) {
            areg = asrc[(c + 1) * 4];
            breg0 = bsrc[(c + 1) * 4 + b_half];
            breg1 = bsrc[(c + 1) * 4 + 2 + b_half];
        }
        __syncthreads();

#pragma unroll
        for (int ks = 0; ks < 2; ks++) {
            int wcol = ks * 8 + 2 * tig;
            uint2 aA0 = *(const uint2*)&a_pack[buf][(wq0 + frow) * PCKH + wcol];
            uint2 aA1 = *(const uint2*)&a_pack[buf][(wq0 + 8 + frow) * PCKH + wcol];
            uint2 aB0 = *(const uint2*)&a_pack[buf][(wq0 + 16 + frow) * PCKH + wcol];
            uint2 aB1 = *(const uint2*)&a_pack[buf][(wq0 + 24 + frow) * PCKH + wcol];
#pragma unroll
            for (int nt = 0; nt < 4; nt++) {
                uint2 bb =
                    *(const uint2*)&b_pack[buf][(oh + nt * 8 + frow) * PCKH + wcol];
                mma_f16(acc[0][nt], aA0.x, aA1.x, aA0.y, aA1.y, bb.x, bb.y);
                mma_f16(acc[1][nt], aB0.x, aB1.x, aB0.y, aB1.y, bb.x, bb.y);
            }
        }
        __syncthreads();
    }

#pragma unroll
    for (int qb = 0; qb < 2; qb++)
#pragma unroll
        for (int nt = 0; nt < 4; nt++) {
            int rr = row0 + wq0 + qb * 16 + frow;
            int oo = oh + nt * 8 + fcol;
            float b0 = bias_s[oo], b1 = bias_s[oo + 1];
            float* p0 = out + (size_t)rr * DD + oo;
            *(float2*)p0 = make_float2(acc[qb][nt][0] + b0, acc[qb][nt][1] + b1);
            *(float2*)(p0 + (size_t)8 * DD) =
                make_float2(acc[qb][nt][2] + b0, acc[qb][nt][3] + b1);
        }
}

// ============================================================
extern "C" void kernel_launch(void* const* d_in, const int* in_sizes, int n_in,
                              void* d_out, int out_size) {
    const float* x    = (const float*)d_in[0];
    const int*   adj  = (const int*)d_in[1];
    const float* W    = (const float*)d_in[2];
    const float* a    = (const float*)d_in[3];
    const float* Wp   = (const float*)d_in[4];
    const float* bias = (const float*)d_in[5];

    const size_t OUT_E = (size_t)BB * NN * DD;
    const size_t AL_E  = (size_t)BB * HH * NN * NN;

    float* outp = nullptr;
    float* alphap = nullptr;
    int write_alpha = 0, write_out = 0;

    if ((size_t)out_size >= OUT_E + AL_E) {
        outp = (float*)d_out;
        alphap = (float*)d_out + OUT_E;
        write_alpha = 1;
        write_out = 1;
    } else if ((size_t)out_size >= AL_E) {
        alphap = (float*)d_out;
        write_alpha = 1;
    } else {
        outp = (float*)d_out;
        write_out = 1;
    }
    if (!alphap) alphap = g_h;  // dummy, never stored to when !write_alpha

    // k_attn is launch #4 so ncu (-s based) profiles it
    k_packadj<<<(BB * NN) / 8, 256>>>(adj);
    k_project<<<dim3(NN / 16, BB), 256>>>(x, W);
    k_scores<<<(BB * HH * NN * 32) / 256, 256>>>(a);
    k_attn_mma<<<dim3(NN / QB, HH, BB), 256>>>(alphap, write_alpha);
    if (write_out) {
        k_prepw<<<128, 256>>>(Wp);
        k_outproj_f16<<<(BB * NN) / QBO, 256>>>(bias, outp);
    }
}